// round 1
// baseline (speedup 1.0000x reference)
#include <cuda_runtime.h>

#define BB 16
#define SS 2048
#define HH 1024
#define DD 64
#define RR 2048
#define M_TOTAL (BB*SS)          // 32768 rows
#define NN (2*DD)                // 128 output cols (q | k)

// Scratch for rotated q/k: [B*S, 64] each, fp32 (8.4 MB each)
__device__ float g_Q[M_TOTAL * DD];
__device__ float g_K[M_TOTAL * DD];

// ---------------------------------------------------------------------------
// Kernel 1: C = A @ W + b, fused RoPE, split-store to g_Q / g_K
// BM=64, BN=128, BK=16, 256 threads, per-thread micro-tile 8x4
// ---------------------------------------------------------------------------
#define BM 64
#define BN 128
#define BK 16

__global__ __launch_bounds__(256) void gemm_rope_kernel(
    const float* __restrict__ A,      // [M_TOTAL, H]
    const float* __restrict__ W,      // [H, 128]
    const float* __restrict__ bias,   // [128]
    const int*   __restrict__ pos_ids // [M_TOTAL]
) {
    __shared__ float As[BK][BM];      // transposed A tile
    __shared__ float Ws[BK][BN];

    const int tid  = threadIdx.x;
    const int trow = tid >> 5;        // 0..7  -> 8 rows each
    const int tcol = tid & 31;        // 0..31 -> 4 cols each
    const int blockM = blockIdx.x * BM;

    float acc[8][4];
#pragma unroll
    for (int i = 0; i < 8; ++i)
#pragma unroll
        for (int j = 0; j < 4; ++j) acc[i][j] = 0.0f;

    // A-load mapping: each thread loads one float4 per tile
    const int a_row = tid >> 2;       // 0..63
    const int a_k4  = tid & 3;        // 0..3 (float4 within 16-wide K tile)
    // W-load mapping: each thread loads two float4
    const int w_row0 = tid >> 5;           // 0..7
    const int w_col4 = tid & 31;           // 0..31

    const int num_kt = HH / BK;       // 64
    for (int kt = 0; kt < num_kt; ++kt) {
        const int k0 = kt * BK;
        // load A tile (transposed into SMEM)
        float4 av = *reinterpret_cast<const float4*>(
            &A[(size_t)(blockM + a_row) * HH + k0 + a_k4 * 4]);
        As[a_k4 * 4 + 0][a_row] = av.x;
        As[a_k4 * 4 + 1][a_row] = av.y;
        As[a_k4 * 4 + 2][a_row] = av.z;
        As[a_k4 * 4 + 3][a_row] = av.w;
        // load W tile (row-major)
        float4 wv0 = *reinterpret_cast<const float4*>(
            &W[(size_t)(k0 + w_row0) * NN + w_col4 * 4]);
        float4 wv1 = *reinterpret_cast<const float4*>(
            &W[(size_t)(k0 + w_row0 + 8) * NN + w_col4 * 4]);
        *reinterpret_cast<float4*>(&Ws[w_row0][w_col4 * 4])     = wv0;
        *reinterpret_cast<float4*>(&Ws[w_row0 + 8][w_col4 * 4]) = wv1;
        __syncthreads();

#pragma unroll
        for (int kk = 0; kk < BK; ++kk) {
            float4 a0 = *reinterpret_cast<const float4*>(&As[kk][trow * 8]);
            float4 a1 = *reinterpret_cast<const float4*>(&As[kk][trow * 8 + 4]);
            float4 wv = *reinterpret_cast<const float4*>(&Ws[kk][tcol * 4]);
            float am[8] = {a0.x, a0.y, a0.z, a0.w, a1.x, a1.y, a1.z, a1.w};
            float wm[4] = {wv.x, wv.y, wv.z, wv.w};
#pragma unroll
            for (int i = 0; i < 8; ++i)
#pragma unroll
                for (int j = 0; j < 4; ++j)
                    acc[i][j] = fmaf(am[i], wm[j], acc[i][j]);
        }
        __syncthreads();
    }

    // Epilogue: bias + RoPE + split store.
    const int colbase = tcol * 4;                 // multiple of 4 -> 2 rotation pairs
    const bool is_q   = (colbase < DD);
    const int dloc    = is_q ? colbase : colbase - DD;   // local dim within q or k half
    // inv_freq for the two pairs this thread owns (depends only on column)
    const float LN1E4_OVER_32 = 0.28782313662425574f;    // ln(10000)/32
    const float f0 = __expf(-(float)(dloc / 2)     * LN1E4_OVER_32);
    const float f1 = __expf(-(float)(dloc / 2 + 1) * LN1E4_OVER_32);
    const float b0 = bias[colbase + 0];
    const float b1 = bias[colbase + 1];
    const float b2 = bias[colbase + 2];
    const float b3 = bias[colbase + 3];
    float* dst = is_q ? g_Q : g_K;

#pragma unroll
    for (int i = 0; i < 8; ++i) {
        const int g = blockM + trow * 8 + i;
        const float pos = (float)pos_ids[g];
        float s0, c0, s1, c1;
        sincosf(pos * f0, &s0, &c0);
        sincosf(pos * f1, &s1, &c1);
        const float x0 = acc[i][0] + b0;
        const float x1 = acc[i][1] + b1;
        const float x2 = acc[i][2] + b2;
        const float x3 = acc[i][3] + b3;
        float4 y;
        y.x = x0 * c0 - x1 * s0;
        y.y = x1 * c0 + x0 * s0;
        y.z = x2 * c1 - x3 * s1;
        y.w = x3 * c1 + x2 * s1;
        *reinterpret_cast<float4*>(&dst[(size_t)g * DD + dloc]) = y;
    }
}

// ---------------------------------------------------------------------------
// Kernel 2: per-relation gather + dot + mask.  One warp per relation.
// ---------------------------------------------------------------------------
__global__ __launch_bounds__(256) void relation_kernel(
    const int*   __restrict__ rel_idx,  // [B*R, 4]
    const float* __restrict__ mask,     // [B*R]
    float*       __restrict__ out       // [B*R]
) {
    const int warp = (blockIdx.x * blockDim.x + threadIdx.x) >> 5;
    const int lane = threadIdx.x & 31;
    if (warp >= BB * RR) return;

    const int b    = warp / RR;
    const int4 idx = reinterpret_cast<const int4*>(rel_idx)[warp];
    const int base = b * SS;

    const float2* q0 = reinterpret_cast<const float2*>(&g_Q[(size_t)(base + idx.x) * DD]);
    const float2* q1 = reinterpret_cast<const float2*>(&g_Q[(size_t)(base + idx.y) * DD]);
    const float2* k2 = reinterpret_cast<const float2*>(&g_K[(size_t)(base + idx.z) * DD]);
    const float2* k3 = reinterpret_cast<const float2*>(&g_K[(size_t)(base + idx.w) * DD]);

    float2 a = q0[lane], c = k2[lane];
    float sum = a.x * c.x + a.y * c.y;
    a = q1[lane]; c = k3[lane];
    sum += a.x * c.x + a.y * c.y;

#pragma unroll
    for (int off = 16; off > 0; off >>= 1)
        sum += __shfl_xor_sync(0xffffffffu, sum, off);

    if (lane == 0) {
        const float m = mask[warp];
        out[warp] = (sum + (1.0f - m) * -1e12f) * 0.125f;  // 1/sqrt(64)
    }
}

extern "C" void kernel_launch(void* const* d_in, const int* in_sizes, int n_in,
                              void* d_out, int out_size) {
    const float* lhs  = (const float*)d_in[0];   // [B,S,H]
    const float* W    = (const float*)d_in[1];   // [H,128]
    const float* bias = (const float*)d_in[2];   // [128]
    const int*   pos  = (const int*)d_in[3];     // [B,S]
    const int*   ridx = (const int*)d_in[4];     // [B,R,4]
    const float* lm   = (const float*)d_in[5];   // [B,R]
    float* out = (float*)d_out;                  // [B,R]

    gemm_rope_kernel<<<M_TOTAL / BM, 256>>>(lhs, W, bias, pos);
    relation_kernel<<<(BB * RR + 7) / 8, 256>>>(ridx, lm, out);
}

// round 2
// speedup vs baseline: 1.0488x; 1.0488x over previous
#include <cuda_runtime.h>

#define BB 16
#define SS 2048
#define HH 1024
#define DD 64
#define RR 2048
#define M_TOTAL (BB*SS)          // 32768 rows
#define NN (2*DD)                // 128 output cols (q | k)

// Scratch for rotated q/k: [B*S, 64] each, fp32
__device__ float g_Q[M_TOTAL * DD];
__device__ float g_K[M_TOTAL * DD];

typedef unsigned long long u64;

// ---- packed fp32x2 helpers (sm_103a FFMA2 path, PTX-only) -----------------
__device__ __forceinline__ u64 pack_dup(float x) {
    u64 r; unsigned int u = __float_as_uint(x);
    asm("mov.b64 %0, {%1, %1};" : "=l"(r) : "r"(u));
    return r;
}
__device__ __forceinline__ void fma2(u64& d, u64 a, u64 b) {
    asm("fma.rn.f32x2 %0, %1, %2, %0;" : "+l"(d) : "l"(a), "l"(b));
}
__device__ __forceinline__ float2 unpack2(u64 v) {
    unsigned int lo, hi;
    asm("mov.b64 {%0, %1}, %2;" : "=r"(lo), "=r"(hi) : "l"(v));
    return make_float2(__uint_as_float(lo), __uint_as_float(hi));
}

// ---------------------------------------------------------------------------
// Kernel 1: C = A @ W + b, fused RoPE, split-store to g_Q / g_K
// BM=128, BN=128, BK=16, 256 threads, micro-tile 8x8 per thread, f32x2 FMA
// ---------------------------------------------------------------------------
#define BM 128
#define BN 128
#define BK 16
#define BMP (BM + 4)             // pad to soften STS conflicts

__global__ __launch_bounds__(256) void gemm_rope_kernel(
    const float* __restrict__ A,      // [M_TOTAL, H]
    const float* __restrict__ W,      // [H, 128]
    const float* __restrict__ bias,   // [128]
    const int*   __restrict__ pos_ids // [M_TOTAL]
) {
    __shared__ float As[BK][BMP];     // transposed A tile
    __shared__ float Ws[BK][BN];

    const int tid = threadIdx.x;
    const int tx  = tid & 15;         // 0..15 -> 8 cols each
    const int ty  = tid >> 4;         // 0..15 -> 8 rows each
    const int blockM = blockIdx.x * BM;

    u64 acc2[8][4];
#pragma unroll
    for (int i = 0; i < 8; ++i)
#pragma unroll
        for (int j = 0; j < 4; ++j) acc2[i][j] = 0ull;

    // A-load mapping: each thread loads two float4 (rows r and r+64)
    const int a_row = tid >> 2;       // 0..63
    const int a_k4  = tid & 3;        // float4 within 16-wide K slab
    // W-load mapping: each thread loads two float4 (k-rows r and r+8)
    const int w_row = tid >> 5;       // 0..7
    const int w_c4  = tid & 31;       // 0..31

    const int num_kt = HH / BK;       // 64
    for (int kt = 0; kt < num_kt; ++kt) {
        const int k0 = kt * BK;
        float4 av0 = *reinterpret_cast<const float4*>(
            &A[(size_t)(blockM + a_row) * HH + k0 + a_k4 * 4]);
        float4 av1 = *reinterpret_cast<const float4*>(
            &A[(size_t)(blockM + a_row + 64) * HH + k0 + a_k4 * 4]);
        As[a_k4 * 4 + 0][a_row]      = av0.x;
        As[a_k4 * 4 + 1][a_row]      = av0.y;
        As[a_k4 * 4 + 2][a_row]      = av0.z;
        As[a_k4 * 4 + 3][a_row]      = av0.w;
        As[a_k4 * 4 + 0][a_row + 64] = av1.x;
        As[a_k4 * 4 + 1][a_row + 64] = av1.y;
        As[a_k4 * 4 + 2][a_row + 64] = av1.z;
        As[a_k4 * 4 + 3][a_row + 64] = av1.w;

        float4 wv0 = *reinterpret_cast<const float4*>(
            &W[(size_t)(k0 + w_row) * NN + w_c4 * 4]);
        float4 wv1 = *reinterpret_cast<const float4*>(
            &W[(size_t)(k0 + w_row + 8) * NN + w_c4 * 4]);
        *reinterpret_cast<float4*>(&Ws[w_row][w_c4 * 4])     = wv0;
        *reinterpret_cast<float4*>(&Ws[w_row + 8][w_c4 * 4]) = wv1;
        __syncthreads();

#pragma unroll
        for (int kk = 0; kk < BK; ++kk) {
            float4 a0 = *reinterpret_cast<const float4*>(&As[kk][ty * 8]);
            float4 a1 = *reinterpret_cast<const float4*>(&As[kk][ty * 8 + 4]);
            ulonglong2 wl0 = *reinterpret_cast<const ulonglong2*>(&Ws[kk][tx * 8]);
            ulonglong2 wl1 = *reinterpret_cast<const ulonglong2*>(&Ws[kk][tx * 8 + 4]);
            u64 w2[4] = {wl0.x, wl0.y, wl1.x, wl1.y};
            u64 ap[8];
            ap[0] = pack_dup(a0.x); ap[1] = pack_dup(a0.y);
            ap[2] = pack_dup(a0.z); ap[3] = pack_dup(a0.w);
            ap[4] = pack_dup(a1.x); ap[5] = pack_dup(a1.y);
            ap[6] = pack_dup(a1.z); ap[7] = pack_dup(a1.w);
#pragma unroll
            for (int i = 0; i < 8; ++i)
#pragma unroll
                for (int j = 0; j < 4; ++j)
                    fma2(acc2[i][j], ap[i], w2[j]);
        }
        __syncthreads();
    }

    // Epilogue: bias + RoPE + split store. Thread owns 8 cols tx*8..tx*8+7.
    const int  c0   = tx * 8;
    const bool is_q = (c0 < DD);
    const int  dloc = c0 & (DD - 1);
    const float LN1E4_OVER_32 = 0.28782313662425574f;   // ln(10000)/32
    float fr[4], bs[8];
#pragma unroll
    for (int p = 0; p < 4; ++p)
        fr[p] = __expf(-(float)(dloc / 2 + p) * LN1E4_OVER_32);
#pragma unroll
    for (int j = 0; j < 8; ++j) bs[j] = bias[c0 + j];
    float* dst = is_q ? g_Q : g_K;

#pragma unroll
    for (int i = 0; i < 8; ++i) {
        const int g = blockM + ty * 8 + i;
        const float pos = (float)pos_ids[g];
        float y[8];
#pragma unroll
        for (int p = 0; p < 4; ++p) {
            float2 xv = unpack2(acc2[i][p]);
            const float x0 = xv.x + bs[2 * p];
            const float x1 = xv.y + bs[2 * p + 1];
            float s, c;
            sincosf(pos * fr[p], &s, &c);
            y[2 * p]     = x0 * c - x1 * s;
            y[2 * p + 1] = x1 * c + x0 * s;
        }
        float4* o = reinterpret_cast<float4*>(&dst[(size_t)g * DD + dloc]);
        o[0] = make_float4(y[0], y[1], y[2], y[3]);
        o[1] = make_float4(y[4], y[5], y[6], y[7]);
    }
}

// ---------------------------------------------------------------------------
// Kernel 2: per-relation gather + dot + mask.  One warp per relation.
// ---------------------------------------------------------------------------
__global__ __launch_bounds__(256) void relation_kernel(
    const int*   __restrict__ rel_idx,  // [B*R, 4]
    const float* __restrict__ mask,     // [B*R]
    float*       __restrict__ out       // [B*R]
) {
    const int warp = (blockIdx.x * blockDim.x + threadIdx.x) >> 5;
    const int lane = threadIdx.x & 31;
    if (warp >= BB * RR) return;

    const int b    = warp / RR;
    const int4 idx = reinterpret_cast<const int4*>(rel_idx)[warp];
    const int base = b * SS;

    const float2* q0 = reinterpret_cast<const float2*>(&g_Q[(size_t)(base + idx.x) * DD]);
    const float2* q1 = reinterpret_cast<const float2*>(&g_Q[(size_t)(base + idx.y) * DD]);
    const float2* k2 = reinterpret_cast<const float2*>(&g_K[(size_t)(base + idx.z) * DD]);
    const float2* k3 = reinterpret_cast<const float2*>(&g_K[(size_t)(base + idx.w) * DD]);

    float2 a = q0[lane], c = k2[lane];
    float sum = a.x * c.x + a.y * c.y;
    a = q1[lane]; c = k3[lane];
    sum += a.x * c.x + a.y * c.y;

#pragma unroll
    for (int off = 16; off > 0; off >>= 1)
        sum += __shfl_xor_sync(0xffffffffu, sum, off);

    if (lane == 0) {
        const float m = mask[warp];
        out[warp] = (sum + (1.0f - m) * -1e12f) * 0.125f;  // 1/sqrt(64)
    }
}

extern "C" void kernel_launch(void* const* d_in, const int* in_sizes, int n_in,
                              void* d_out, int out_size) {
    const float* lhs  = (const float*)d_in[0];   // [B,S,H]
    const float* W    = (const float*)d_in[1];   // [H,128]
    const float* bias = (const float*)d_in[2];   // [128]
    const int*   pos  = (const int*)d_in[3];     // [B,S]
    const int*   ridx = (const int*)d_in[4];     // [B,R,4]
    const float* lm   = (const float*)d_in[5];   // [B,R]
    float* out = (float*)d_out;                  // [B,R]

    gemm_rope_kernel<<<M_TOTAL / BM, 256>>>(lhs, W, bias, pos);
    relation_kernel<<<(BB * RR + 7) / 8, 256>>>(ridx, lm, out);
}

// round 4
// speedup vs baseline: 1.7142x; 1.6345x over previous
#include <cuda_runtime.h>
#include <cuda_bf16.h>
#include <cstdint>

#define BB 16
#define SS 2048
#define HH 1024
#define DD 64
#define RR 2048
#define M_TOTAL (BB*SS)          // 32768 rows
#define NN 128                   // output cols (q | k)

#define BM 128
#define BN 128
#define BK 32
#define BKP 40                   // padded row length in bf16 (80B -> 20-bank stride)
#define NKT (HH/BK)              // 32 k-chunks

// Scratch
__device__ float g_Q[M_TOTAL * DD];
__device__ float g_K[M_TOTAL * DD];
__device__ __nv_bfloat16 g_Wt_hi[NN * HH];   // W^T hi, [128][1024] K-major
__device__ __nv_bfloat16 g_Wt_lo[NN * HH];   // W^T lo

// ---------------- helpers ----------------
__device__ __forceinline__ uint32_t smem_u32(const void* p) {
    uint32_t a;
    asm("{ .reg .u64 t; cvta.to.shared.u64 t, %1; cvt.u32.u64 %0, t; }"
        : "=r"(a) : "l"(p));
    return a;
}
// pack bf16(lo),bf16(hi): first PTX source lands in HIGH half
__device__ __forceinline__ uint32_t f2bf2(float lo, float hi) {
    uint32_t r;
    asm("cvt.rn.bf16x2.f32 %0, %1, %2;" : "=r"(r) : "f"(hi), "f"(lo));
    return r;
}
__device__ __forceinline__ void bsplit2(float x, float y, uint32_t& h, uint32_t& l) {
    h = f2bf2(x, y);
    float hx = __uint_as_float(h << 16);
    float hy = __uint_as_float(h & 0xffff0000u);
    l = f2bf2(x - hx, y - hy);
}
__device__ __forceinline__ void sts64(uint32_t addr, uint32_t a, uint32_t b) {
    asm volatile("st.shared.v2.b32 [%0], {%1,%2};" :: "r"(addr), "r"(a), "r"(b) : "memory");
}
__device__ __forceinline__ void sts128(uint32_t addr, uint4 v) {
    asm volatile("st.shared.v4.b32 [%0], {%1,%2,%3,%4};"
                 :: "r"(addr), "r"(v.x), "r"(v.y), "r"(v.z), "r"(v.w) : "memory");
}
__device__ __forceinline__ void ldsm4(uint32_t addr, uint32_t& r0, uint32_t& r1,
                                      uint32_t& r2, uint32_t& r3) {
    asm volatile("ldmatrix.sync.aligned.m8n8.x4.shared.b16 {%0,%1,%2,%3}, [%4];"
                 : "=r"(r0), "=r"(r1), "=r"(r2), "=r"(r3) : "r"(addr));
}
__device__ __forceinline__ void mma16816(float* c, uint32_t a0, uint32_t a1,
                                         uint32_t a2, uint32_t a3,
                                         uint32_t b0, uint32_t b1) {
    asm volatile(
        "mma.sync.aligned.m16n8k16.row.col.f32.bf16.bf16.f32 "
        "{%0,%1,%2,%3}, {%4,%5,%6,%7}, {%8,%9}, {%0,%1,%2,%3};"
        : "+f"(c[0]), "+f"(c[1]), "+f"(c[2]), "+f"(c[3])
        : "r"(a0), "r"(a1), "r"(a2), "r"(a3), "r"(b0), "r"(b1));
}

// ---------------------------------------------------------------------------
// Prep: W [1024][128] fp32 -> Wt_hi/Wt_lo [128][1024] bf16 (transpose + split)
// ---------------------------------------------------------------------------
__global__ __launch_bounds__(256) void prep_w_kernel(const float* __restrict__ W) {
    int idx = blockIdx.x * 256 + threadIdx.x;        // 131072 total
    int k = idx >> 7, n = idx & 127;
    float w = W[idx];
    __nv_bfloat16 h = __float2bfloat16(w);
    g_Wt_hi[n * HH + k] = h;
    g_Wt_lo[n * HH + k] = __float2bfloat16(w - __bfloat162float(h));
}

// ---------------------------------------------------------------------------
// GEMM via mma.sync (bf16 3-term split), fused bias + RoPE epilogue.
// CTA: M=128, N=128, K=1024. 8 warps (2x4), warp tile 64x32.
// ---------------------------------------------------------------------------
__global__ __launch_bounds__(256, 2) void gemm_mma_kernel(
    const float* __restrict__ A,       // [M_TOTAL, 1024]
    const float* __restrict__ bias,    // [128]
    const int*   __restrict__ pos_ids  // [M_TOTAL]
) {
    __shared__ __nv_bfloat16 AsH[BM * BKP], AsL[BM * BKP];
    __shared__ __nv_bfloat16 BsH[BN * BKP], BsL[BN * BKP];

    const int tid  = threadIdx.x;
    const int lane = tid & 31;
    const int warp = tid >> 5;
    const int wm   = warp >> 2;       // 0..1
    const int wn   = warp & 3;        // 0..3
    const int blockM = blockIdx.x * BM;

    float acc[4][4][4];
#pragma unroll
    for (int m = 0; m < 4; ++m)
#pragma unroll
        for (int n = 0; n < 4; ++n)
#pragma unroll
            for (int f = 0; f < 4; ++f) acc[m][n][f] = 0.0f;

    // ---- global load mappings ----
    const int arow0 = tid >> 3;       // 0..31 (rows arow0 + 32*i)
    const int af    = tid & 7;        // float4 index within 32-float k-chunk
    const int bn    = tid & 127;      // B row (n)
    const int bp    = tid >> 7;       // 0..1: 16-element half of 32-wide chunk

    const uint32_t sAH = smem_u32(AsH), sAL = smem_u32(AsL);
    const uint32_t sBH = smem_u32(BsH), sBL = smem_u32(BsL);

    float4 aldg[4];
    uint4  bh0, bh1, bl0, bl1;

    // ldmatrix source addresses (fixed per thread, chunk-local)
    const int a_lr   = lane & 7;
    const int a_tile = lane >> 3;
    // A tile for mtile m at k16 kk: row = wm*64 + m*16 + (a_tile&1)*8 + a_lr,
    //                               col = kk + (a_tile>>1)*8
    const uint32_t a_addr_base =
        (uint32_t)(((wm * 64 + (a_tile & 1) * 8 + a_lr) * BKP + (a_tile >> 1) * 8) * 2);
    // B tiles (pair of n8) for n2 at kk: row = wn*32 + n2*16 + (a_tile>>1)*8 + a_lr,
    //                                    col = kk + (a_tile&1)*8
    const uint32_t b_addr_base =
        (uint32_t)(((wn * 32 + (a_tile >> 1) * 8 + a_lr) * BKP + (a_tile & 1) * 8) * 2);

    // ---- prologue: load chunk 0 ----
    {
        const float4* Ag = reinterpret_cast<const float4*>(A);
#pragma unroll
        for (int i = 0; i < 4; ++i)
            aldg[i] = Ag[((size_t)(blockM + arow0 + 32 * i) * HH) / 4 + af];
        const uint4* Bh = reinterpret_cast<const uint4*>(&g_Wt_hi[(size_t)bn * HH + bp * 16]);
        const uint4* Bl = reinterpret_cast<const uint4*>(&g_Wt_lo[(size_t)bn * HH + bp * 16]);
        bh0 = Bh[0]; bh1 = Bh[1]; bl0 = Bl[0]; bl1 = Bl[1];
    }

    for (int kt = 0; kt < NKT; ++kt) {
        if (kt) __syncthreads();           // previous compute done -> smem reusable

        // ---- STS: A convert+split, B copy ----
#pragma unroll
        for (int i = 0; i < 4; ++i) {
            uint32_t h0, l0, h1, l1;
            bsplit2(aldg[i].x, aldg[i].y, h0, l0);
            bsplit2(aldg[i].z, aldg[i].w, h1, l1);
            uint32_t off = (uint32_t)(((arow0 + 32 * i) * BKP + af * 4) * 2);
            sts64(sAH + off, h0, h1);
            sts64(sAL + off, l0, l1);
        }
        {
            uint32_t off = (uint32_t)((bn * BKP + bp * 16) * 2);
            sts128(sBH + off, bh0);
            sts128(sBH + off + 16, bh1);
            sts128(sBL + off, bl0);
            sts128(sBL + off + 16, bl1);
        }
        __syncthreads();

        // ---- prefetch next chunk while computing ----
        if (kt + 1 < NKT) {
            const int k0 = (kt + 1) * BK;
            const float4* Ag = reinterpret_cast<const float4*>(A);
#pragma unroll
            for (int i = 0; i < 4; ++i)
                aldg[i] = Ag[((size_t)(blockM + arow0 + 32 * i) * HH + k0) / 4 + af];
            const uint4* Bh =
                reinterpret_cast<const uint4*>(&g_Wt_hi[(size_t)bn * HH + k0 + bp * 16]);
            const uint4* Bl =
                reinterpret_cast<const uint4*>(&g_Wt_lo[(size_t)bn * HH + k0 + bp * 16]);
            bh0 = Bh[0]; bh1 = Bh[1]; bl0 = Bl[0]; bl1 = Bl[1];
        }

        // ---- compute: 2 k16 steps, 3 split terms ----
#pragma unroll
        for (int kk = 0; kk < BK; kk += 16) {
            uint32_t bh[2][4], bl[2][4];
#pragma unroll
            for (int n2 = 0; n2 < 2; ++n2) {
                uint32_t boff = b_addr_base + (uint32_t)((n2 * 16 * BKP + kk) * 2);
                ldsm4(sBH + boff, bh[n2][0], bh[n2][1], bh[n2][2], bh[n2][3]);
                ldsm4(sBL + boff, bl[n2][0], bl[n2][1], bl[n2][2], bl[n2][3]);
            }
#pragma unroll
            for (int m = 0; m < 4; ++m) {
                uint32_t aoff = a_addr_base + (uint32_t)((m * 16 * BKP + kk) * 2);
                uint32_t ah0, ah1, ah2, ah3, al0, al1, al2, al3;
                ldsm4(sAH + aoff, ah0, ah1, ah2, ah3);
                ldsm4(sAL + aoff, al0, al1, al2, al3);
#pragma unroll
                for (int n = 0; n < 4; ++n) {
                    uint32_t b0 = bh[n >> 1][(n & 1) * 2];
                    uint32_t b1 = bh[n >> 1][(n & 1) * 2 + 1];
                    uint32_t c0 = bl[n >> 1][(n & 1) * 2];
                    uint32_t c1 = bl[n >> 1][(n & 1) * 2 + 1];
                    mma16816(acc[m][n], ah0, ah1, ah2, ah3, b0, b1);  // Ah*Bh
                    mma16816(acc[m][n], ah0, ah1, ah2, ah3, c0, c1);  // Ah*Bl
                    mma16816(acc[m][n], al0, al1, al2, al3, b0, b1);  // Al*Bh
                }
            }
        }
    }

    // ---- epilogue: bias + RoPE + split store (all in registers) ----
    const float LN1E4_OVER_32 = 0.28782313662425574f;   // ln(10000)/32
#pragma unroll
    for (int n = 0; n < 4; ++n) {
        const int col  = wn * 32 + n * 8 + (lane & 3) * 2;   // even
        const bool is_q = (col < DD);
        const int dloc  = col & (DD - 1);
        const float fr  = __expf(-(float)(dloc >> 1) * LN1E4_OVER_32);
        const float b0 = bias[col], b1 = bias[col + 1];
        float* dst = is_q ? g_Q : g_K;
#pragma unroll
        for (int m = 0; m < 4; ++m) {
            const int ra = blockM + wm * 64 + m * 16 + (lane >> 2);
#pragma unroll
            for (int h = 0; h < 2; ++h) {
                const int r = ra + h * 8;
                const float pos = (float)__ldg(&pos_ids[r]);
                float s, c;
                sincosf(pos * fr, &s, &c);
                const float x0 = acc[m][n][2 * h]     + b0;
                const float x1 = acc[m][n][2 * h + 1] + b1;
                float2 y = make_float2(x0 * c - x1 * s, x1 * c + x0 * s);
                *reinterpret_cast<float2*>(&dst[(size_t)r * DD + dloc]) = y;
            }
        }
    }
}

// ---------------------------------------------------------------------------
// Relation gather + dot + mask. One warp per relation.
// ---------------------------------------------------------------------------
__global__ __launch_bounds__(256) void relation_kernel(
    const int*   __restrict__ rel_idx,  // [B*R, 4]
    const float* __restrict__ mask,     // [B*R]
    float*       __restrict__ out       // [B*R]
) {
    const int warp = (blockIdx.x * blockDim.x + threadIdx.x) >> 5;
    const int lane = threadIdx.x & 31;
    if (warp >= BB * RR) return;

    const int b    = warp / RR;
    const int4 idx = reinterpret_cast<const int4*>(rel_idx)[warp];
    const int base = b * SS;

    const float2* q0 = reinterpret_cast<const float2*>(&g_Q[(size_t)(base + idx.x) * DD]);
    const float2* q1 = reinterpret_cast<const float2*>(&g_Q[(size_t)(base + idx.y) * DD]);
    const float2* k2 = reinterpret_cast<const float2*>(&g_K[(size_t)(base + idx.z) * DD]);
    const float2* k3 = reinterpret_cast<const float2*>(&g_K[(size_t)(base + idx.w) * DD]);

    float2 a = q0[lane], c = k2[lane];
    float sum = a.x * c.x + a.y * c.y;
    a = q1[lane]; c = k3[lane];
    sum += a.x * c.x + a.y * c.y;

#pragma unroll
    for (int off = 16; off > 0; off >>= 1)
        sum += __shfl_xor_sync(0xffffffffu, sum, off);

    if (lane == 0) {
        const float m = mask[warp];
        out[warp] = (sum + (1.0f - m) * -1e12f) * 0.125f;  // 1/sqrt(64)
    }
}

extern "C" void kernel_launch(void* const* d_in, const int* in_sizes, int n_in,
                              void* d_out, int out_size) {
    const float* lhs  = (const float*)d_in[0];   // [B,S,H]
    const float* W    = (const float*)d_in[1];   // [H,128]
    const float* bias = (const float*)d_in[2];   // [128]
    const int*   pos  = (const int*)d_in[3];     // [B,S]
    const int*   ridx = (const int*)d_in[4];     // [B,R,4]
    const float* lm   = (const float*)d_in[5];   // [B,R]
    float* out = (float*)d_out;                  // [B,R]

    prep_w_kernel<<<512, 256>>>(W);
    gemm_mma_kernel<<<M_TOTAL / BM, 256>>>(lhs, bias, pos);
    relation_kernel<<<(BB * RR + 7) / 8, 256>>>(ridx, lm, out);
}

// round 5
// speedup vs baseline: 2.0313x; 1.1850x over previous
#include <cuda_runtime.h>
#include <cuda_bf16.h>
#include <cstdint>

#define BB 16
#define SS 2048
#define HH 1024
#define DD 64
#define RR 2048
#define M_TOTAL (BB*SS)          // 32768 rows
#define NN 128                   // output cols (q | k)

#define BM 128
#define BN 128
#define BK 32
#define BKP 40                   // padded row length in bf16 (80B rows)
#define NKT (HH/BK)              // 32 k-chunks

// dynamic SMEM layout: per buffer [AH AL BH BL], each tile 128*40*2 = 10240 B
#define TILE_B   (128*BKP*2)
#define BUF_B    (4*TILE_B)      // 40960
#define SMEM_DYN (2*BUF_B)       // 81920

// Scratch
__device__ float g_Q[M_TOTAL * DD];
__device__ float g_K[M_TOTAL * DD];
__device__ __nv_bfloat16 g_Wt_hi[NN * HH];   // W^T hi, [128][1024] K-major
__device__ __nv_bfloat16 g_Wt_lo[NN * HH];   // W^T lo

// ---------------- helpers ----------------
__device__ __forceinline__ uint32_t smem_u32(const void* p) {
    uint32_t a;
    asm("{ .reg .u64 t; cvta.to.shared.u64 t, %1; cvt.u32.u64 %0, t; }"
        : "=r"(a) : "l"(p));
    return a;
}
// pack bf16(lo),bf16(hi): first PTX source lands in HIGH half
__device__ __forceinline__ uint32_t f2bf2(float lo, float hi) {
    uint32_t r;
    asm("cvt.rn.bf16x2.f32 %0, %1, %2;" : "=r"(r) : "f"(hi), "f"(lo));
    return r;
}
__device__ __forceinline__ void bsplit2(float x, float y, uint32_t& h, uint32_t& l) {
    h = f2bf2(x, y);
    float hx = __uint_as_float(h << 16);
    float hy = __uint_as_float(h & 0xffff0000u);
    l = f2bf2(x - hx, y - hy);
}
__device__ __forceinline__ void sts64(uint32_t addr, uint32_t a, uint32_t b) {
    asm volatile("st.shared.v2.b32 [%0], {%1,%2};" :: "r"(addr), "r"(a), "r"(b) : "memory");
}
__device__ __forceinline__ void cp16(uint32_t daddr, const void* src) {
    asm volatile("cp.async.cg.shared.global [%0], [%1], 16;"
                 :: "r"(daddr), "l"(src) : "memory");
}
__device__ __forceinline__ void cp_commit() {
    asm volatile("cp.async.commit_group;" ::: "memory");
}
__device__ __forceinline__ void cp_wait0() {
    asm volatile("cp.async.wait_group 0;" ::: "memory");
}
__device__ __forceinline__ void ldsm4(uint32_t addr, uint32_t& r0, uint32_t& r1,
                                      uint32_t& r2, uint32_t& r3) {
    asm volatile("ldmatrix.sync.aligned.m8n8.x4.shared.b16 {%0,%1,%2,%3}, [%4];"
                 : "=r"(r0), "=r"(r1), "=r"(r2), "=r"(r3) : "r"(addr));
}
__device__ __forceinline__ void mma16816(float* c, uint32_t a0, uint32_t a1,
                                         uint32_t a2, uint32_t a3,
                                         uint32_t b0, uint32_t b1) {
    asm volatile(
        "mma.sync.aligned.m16n8k16.row.col.f32.bf16.bf16.f32 "
        "{%0,%1,%2,%3}, {%4,%5,%6,%7}, {%8,%9}, {%0,%1,%2,%3};"
        : "+f"(c[0]), "+f"(c[1]), "+f"(c[2]), "+f"(c[3])
        : "r"(a0), "r"(a1), "r"(a2), "r"(a3), "r"(b0), "r"(b1));
}

// ---------------------------------------------------------------------------
// Prep: W [1024][128] fp32 -> Wt_hi/Wt_lo [128][1024] bf16, tiled transpose
// ---------------------------------------------------------------------------
__global__ __launch_bounds__(256) void prep_w_kernel(const float* __restrict__ W) {
    __shared__ float t[32][33];
    const int k0 = blockIdx.x * 32;       // 32 tiles
    const int n0 = blockIdx.y * 32;       // 4 tiles
    const int r = threadIdx.x >> 5, c = threadIdx.x & 31;
#pragma unroll
    for (int i = 0; i < 4; ++i)
        t[r + 8 * i][c] = W[(size_t)(k0 + r + 8 * i) * NN + n0 + c];
    __syncthreads();
#pragma unroll
    for (int i = 0; i < 4; ++i) {
        const int n = n0 + r + 8 * i, k = k0 + c;
        const float w = t[c][r + 8 * i];
        const __nv_bfloat16 h = __float2bfloat16(w);
        g_Wt_hi[(size_t)n * HH + k] = h;
        g_Wt_lo[(size_t)n * HH + k] = __float2bfloat16(w - __bfloat162float(h));
    }
}

// ---------------------------------------------------------------------------
// GEMM via mma.sync (bf16 3-term split), double-buffered, fused bias + RoPE.
// CTA: M=128, N=128, K=1024. 8 warps (2x4), warp tile 64x32.
// ---------------------------------------------------------------------------
__global__ __launch_bounds__(256, 2) void gemm_mma_kernel(
    const float* __restrict__ A,       // [M_TOTAL, 1024]
    const float* __restrict__ bias,    // [128]
    const int*   __restrict__ pos_ids  // [M_TOTAL]
) {
    extern __shared__ char dsm[];
    const uint32_t sbase = smem_u32(dsm);

    const int tid  = threadIdx.x;
    const int lane = tid & 31;
    const int warp = tid >> 5;
    const int wm   = warp >> 2;       // 0..1
    const int wn   = warp & 3;        // 0..3
    const int blockM = blockIdx.x * BM;

    float acc[4][4][4];
#pragma unroll
    for (int m = 0; m < 4; ++m)
#pragma unroll
        for (int n = 0; n < 4; ++n)
#pragma unroll
            for (int f = 0; f < 4; ++f) acc[m][n][f] = 0.0f;

    // ---- load mappings ----
    const int arow0 = tid >> 3;       // 0..31 (rows arow0 + 32*i)
    const int af    = tid & 7;        // float4 index within 32-float k-chunk
    const int bn    = tid & 127;      // B row (n)
    const int bp    = tid >> 7;       // 0..1: 32B half of the 64B row chunk

    // ldmatrix per-thread address pieces
    const int a_lr   = lane & 7;
    const int a_tile = lane >> 3;
    const uint32_t a_addr_base =
        (uint32_t)(((wm * 64 + (a_tile & 1) * 8 + a_lr) * BKP + (a_tile >> 1) * 8) * 2);
    const uint32_t b_addr_base =
        (uint32_t)(((wn * 32 + (a_tile >> 1) * 8 + a_lr) * BKP + (a_tile & 1) * 8) * 2);

    float4 aldg[4];
    const float4* Ag = reinterpret_cast<const float4*>(A);

    // B cp.async source/dest pieces
    const __nv_bfloat16* bsrc_h = &g_Wt_hi[(size_t)bn * HH + bp * 16];
    const __nv_bfloat16* bsrc_l = &g_Wt_lo[(size_t)bn * HH + bp * 16];
    const uint32_t bdst_off = (uint32_t)(bn * (BKP * 2) + bp * 32);

    // ---- prologue: chunk 0 into buf 0 ----
    {
        const uint32_t buf = sbase;
        cp16(buf + 2 * TILE_B + bdst_off,      bsrc_h);
        cp16(buf + 2 * TILE_B + bdst_off + 16, bsrc_h + 8);
        cp16(buf + 3 * TILE_B + bdst_off,      bsrc_l);
        cp16(buf + 3 * TILE_B + bdst_off + 16, bsrc_l + 8);
        cp_commit();
#pragma unroll
        for (int i = 0; i < 4; ++i)
            aldg[i] = Ag[((size_t)(blockM + arow0 + 32 * i) * HH) / 4 + af];
#pragma unroll
        for (int i = 0; i < 4; ++i) {
            uint32_t h0, l0, h1, l1;
            bsplit2(aldg[i].x, aldg[i].y, h0, l0);
            bsplit2(aldg[i].z, aldg[i].w, h1, l1);
            uint32_t off = (uint32_t)((arow0 + 32 * i) * (BKP * 2) + af * 8);
            sts64(buf + off, h0, h1);
            sts64(buf + TILE_B + off, l0, l1);
        }
        cp_wait0();
        __syncthreads();
    }

    for (int kt = 0; kt < NKT; ++kt) {
        const uint32_t cur = sbase + (kt & 1) * BUF_B;
        const uint32_t nxt = sbase + ((kt + 1) & 1) * BUF_B;
        const bool more = (kt + 1 < NKT);

        if (more) {
            const int k0 = (kt + 1) * BK;
            cp16(nxt + 2 * TILE_B + bdst_off,      bsrc_h + k0);
            cp16(nxt + 2 * TILE_B + bdst_off + 16, bsrc_h + k0 + 8);
            cp16(nxt + 3 * TILE_B + bdst_off,      bsrc_l + k0);
            cp16(nxt + 3 * TILE_B + bdst_off + 16, bsrc_l + k0 + 8);
            cp_commit();
#pragma unroll
            for (int i = 0; i < 4; ++i)
                aldg[i] = Ag[((size_t)(blockM + arow0 + 32 * i) * HH + k0) / 4 + af];
        }

        // ---- compute on cur: 2 k16 steps, 3 split terms ----
        const uint32_t sAH = cur, sAL = cur + TILE_B;
        const uint32_t sBH = cur + 2 * TILE_B, sBL = cur + 3 * TILE_B;
#pragma unroll
        for (int kk = 0; kk < BK; kk += 16) {
            uint32_t bh[2][4], bl[2][4];
#pragma unroll
            for (int n2 = 0; n2 < 2; ++n2) {
                uint32_t boff = b_addr_base + (uint32_t)((n2 * 16 * BKP + kk) * 2);
                ldsm4(sBH + boff, bh[n2][0], bh[n2][1], bh[n2][2], bh[n2][3]);
                ldsm4(sBL + boff, bl[n2][0], bl[n2][1], bl[n2][2], bl[n2][3]);
            }
#pragma unroll
            for (int m = 0; m < 4; ++m) {
                uint32_t aoff = a_addr_base + (uint32_t)((m * 16 * BKP + kk) * 2);
                uint32_t ah0, ah1, ah2, ah3, al0, al1, al2, al3;
                ldsm4(sAH + aoff, ah0, ah1, ah2, ah3);
                ldsm4(sAL + aoff, al0, al1, al2, al3);
#pragma unroll
                for (int n = 0; n < 4; ++n) {
                    uint32_t b0 = bh[n >> 1][(n & 1) * 2];
                    uint32_t b1 = bh[n >> 1][(n & 1) * 2 + 1];
                    uint32_t c0 = bl[n >> 1][(n & 1) * 2];
                    uint32_t c1 = bl[n >> 1][(n & 1) * 2 + 1];
                    mma16816(acc[m][n], ah0, ah1, ah2, ah3, b0, b1);  // Ah*Bh
                    mma16816(acc[m][n], ah0, ah1, ah2, ah3, c0, c1);  // Ah*Bl
                    mma16816(acc[m][n], al0, al1, al2, al3, b0, b1);  // Al*Bh
                }
            }
        }

        if (more) {
#pragma unroll
            for (int i = 0; i < 4; ++i) {
                uint32_t h0, l0, h1, l1;
                bsplit2(aldg[i].x, aldg[i].y, h0, l0);
                bsplit2(aldg[i].z, aldg[i].w, h1, l1);
                uint32_t off = (uint32_t)((arow0 + 32 * i) * (BKP * 2) + af * 8);
                sts64(nxt + off, h0, h1);
                sts64(nxt + TILE_B + off, l0, l1);
            }
            cp_wait0();
        }
        __syncthreads();
    }

    // ---- epilogue: bias + RoPE + split store (all in registers) ----
    const float LN1E4_OVER_32 = 0.28782313662425574f;   // ln(10000)/32
#pragma unroll
    for (int n = 0; n < 4; ++n) {
        const int col  = wn * 32 + n * 8 + (lane & 3) * 2;   // even
        const bool is_q = (col < DD);
        const int dloc  = col & (DD - 1);
        const float fr  = __expf(-(float)(dloc >> 1) * LN1E4_OVER_32);
        const float b0 = bias[col], b1 = bias[col + 1];
        float* dst = is_q ? g_Q : g_K;
#pragma unroll
        for (int m = 0; m < 4; ++m) {
            const int ra = blockM + wm * 64 + m * 16 + (lane >> 2);
#pragma unroll
            for (int h = 0; h < 2; ++h) {
                const int r = ra + h * 8;
                const float pos = (float)__ldg(&pos_ids[r]);
                float s, c;
                sincosf(pos * fr, &s, &c);
                const float x0 = acc[m][n][2 * h]     + b0;
                const float x1 = acc[m][n][2 * h + 1] + b1;
                float2 y = make_float2(x0 * c - x1 * s, x1 * c + x0 * s);
                *reinterpret_cast<float2*>(&dst[(size_t)r * DD + dloc]) = y;
            }
        }
    }
}

// ---------------------------------------------------------------------------
// Relation gather + dot + mask. One warp per relation.
// ---------------------------------------------------------------------------
__global__ __launch_bounds__(256) void relation_kernel(
    const int*   __restrict__ rel_idx,  // [B*R, 4]
    const float* __restrict__ mask,     // [B*R]
    float*       __restrict__ out       // [B*R]
) {
    const int warp = (blockIdx.x * blockDim.x + threadIdx.x) >> 5;
    const int lane = threadIdx.x & 31;
    if (warp >= BB * RR) return;

    const int b    = warp / RR;
    const int4 idx = reinterpret_cast<const int4*>(rel_idx)[warp];
    const int base = b * SS;

    // lanes 0-15: q0.k2 on float4; lanes 16-31: q1.k3
    const int seg  = lane >> 4;          // 0 or 1
    const int sl   = lane & 15;
    const int qrow = base + (seg ? idx.y : idx.x);
    const int krow = base + (seg ? idx.w : idx.z);
    float4 qa = reinterpret_cast<const float4*>(&g_Q[(size_t)qrow * DD])[sl];
    float4 ka = reinterpret_cast<const float4*>(&g_K[(size_t)krow * DD])[sl];
    float sum = qa.x * ka.x + qa.y * ka.y + qa.z * ka.z + qa.w * ka.w;

#pragma unroll
    for (int off = 16; off > 0; off >>= 1)
        sum += __shfl_xor_sync(0xffffffffu, sum, off);

    if (lane == 0) {
        const float m = mask[warp];
        out[warp] = (sum + (1.0f - m) * -1e12f) * 0.125f;  // 1/sqrt(64)
    }
}

extern "C" void kernel_launch(void* const* d_in, const int* in_sizes, int n_in,
                              void* d_out, int out_size) {
    const float* lhs  = (const float*)d_in[0];   // [B,S,H]
    const float* W    = (const float*)d_in[1];   // [H,128]
    const float* bias = (const float*)d_in[2];   // [128]
    const int*   pos  = (const int*)d_in[3];     // [B,S]
    const int*   ridx = (const int*)d_in[4];     // [B,R,4]
    const float* lm   = (const float*)d_in[5];   // [B,R]
    float* out = (float*)d_out;                  // [B,R]

    static bool attr_set = false;
    if (!attr_set) {
        cudaFuncSetAttribute(gemm_mma_kernel,
                             cudaFuncAttributeMaxDynamicSharedMemorySize, SMEM_DYN);
        attr_set = true;
    }
    prep_w_kernel<<<dim3(32, 4), 256>>>(W);
    gemm_mma_kernel<<<M_TOTAL / BM, 256, SMEM_DYN>>>(lhs, bias, pos);
    relation_kernel<<<(BB * RR + 7) / 8, 256>>>(ridx, lm, out);
}

// round 6
// speedup vs baseline: 2.7084x; 1.3333x over previous
#include <cuda_runtime.h>
#include <cuda_fp16.h>
#include <cstdint>

#define BB 16
#define SS 2048
#define HH 1024
#define DD 64
#define RR 2048
#define M_TOTAL (BB*SS)          // 32768 rows
#define NN 128                   // output cols (q | k)

#define BM 128
#define BN 128
#define BK 32
#define BKP 40                   // padded row length in fp16 (80B rows)
#define NKT (HH/BK)              // 32 k-chunks

// dynamic SMEM: per buffer [A16 | WH | WL], each tile 128*40*2 = 10240 B
#define TILE_B   (128*BKP*2)
#define BUF_B    (3*TILE_B)      // 30720
#define SMEM_DYN (2*BUF_B)       // 61440

// Scratch
__device__ float g_Q[M_TOTAL * DD];
__device__ float g_K[M_TOTAL * DD];
__device__ __half g_Wt_h[NN * HH];   // W^T hi fp16, [128][1024] K-major
__device__ __half g_Wt_l[NN * HH];   // W^T lo fp16 (residual)

// ---------------- helpers ----------------
__device__ __forceinline__ uint32_t smem_u32(const void* p) {
    uint32_t a;
    asm("{ .reg .u64 t; cvta.to.shared.u64 t, %1; cvt.u32.u64 %0, t; }"
        : "=r"(a) : "l"(p));
    return a;
}
// pack f16(lo),f16(hi): first PTX source lands in HIGH half
__device__ __forceinline__ uint32_t f2h2(float lo, float hi) {
    uint32_t r;
    asm("cvt.rn.f16x2.f32 %0, %1, %2;" : "=r"(r) : "f"(hi), "f"(lo));
    return r;
}
__device__ __forceinline__ void sts64(uint32_t addr, uint32_t a, uint32_t b) {
    asm volatile("st.shared.v2.b32 [%0], {%1,%2};" :: "r"(addr), "r"(a), "r"(b) : "memory");
}
__device__ __forceinline__ void cp16(uint32_t daddr, const void* src) {
    asm volatile("cp.async.cg.shared.global [%0], [%1], 16;"
                 :: "r"(daddr), "l"(src) : "memory");
}
__device__ __forceinline__ void cp_commit() {
    asm volatile("cp.async.commit_group;" ::: "memory");
}
__device__ __forceinline__ void cp_wait0() {
    asm volatile("cp.async.wait_group 0;" ::: "memory");
}
__device__ __forceinline__ void ldsm4(uint32_t addr, uint32_t& r0, uint32_t& r1,
                                      uint32_t& r2, uint32_t& r3) {
    asm volatile("ldmatrix.sync.aligned.m8n8.x4.shared.b16 {%0,%1,%2,%3}, [%4];"
                 : "=r"(r0), "=r"(r1), "=r"(r2), "=r"(r3) : "r"(addr));
}
__device__ __forceinline__ void mma16816(float* c, uint32_t a0, uint32_t a1,
                                         uint32_t a2, uint32_t a3,
                                         uint32_t b0, uint32_t b1) {
    asm volatile(
        "mma.sync.aligned.m16n8k16.row.col.f32.f16.f16.f32 "
        "{%0,%1,%2,%3}, {%4,%5,%6,%7}, {%8,%9}, {%0,%1,%2,%3};"
        : "+f"(c[0]), "+f"(c[1]), "+f"(c[2]), "+f"(c[3])
        : "r"(a0), "r"(a1), "r"(a2), "r"(a3), "r"(b0), "r"(b1));
}

// ---------------------------------------------------------------------------
// Prep: W [1024][128] fp32 -> Wt_h/Wt_l [128][1024] fp16, tiled transpose
// ---------------------------------------------------------------------------
__global__ __launch_bounds__(256) void prep_w_kernel(const float* __restrict__ W) {
    __shared__ float t[32][33];
    const int k0 = blockIdx.x * 32;       // 32 tiles
    const int n0 = blockIdx.y * 32;       // 4 tiles
    const int r = threadIdx.x >> 5, c = threadIdx.x & 31;
#pragma unroll
    for (int i = 0; i < 4; ++i)
        t[r + 8 * i][c] = W[(size_t)(k0 + r + 8 * i) * NN + n0 + c];
    __syncthreads();
#pragma unroll
    for (int i = 0; i < 4; ++i) {
        const int n = n0 + r + 8 * i, k = k0 + c;
        const float w = t[c][r + 8 * i];
        const __half h = __float2half_rn(w);
        g_Wt_h[(size_t)n * HH + k] = h;
        g_Wt_l[(size_t)n * HH + k] = __float2half_rn(w - __half2float(h));
    }
}

// ---------------------------------------------------------------------------
// GEMM via mma.sync fp16 2-term (A16*Wh + A16*Wl), double-buffered,
// fused bias + RoPE. CTA: M=128, N=128, K=1024. 8 warps (2x4), warp 64x32.
// ---------------------------------------------------------------------------
__global__ __launch_bounds__(256, 2) void gemm_mma_kernel(
    const float* __restrict__ A,       // [M_TOTAL, 1024]
    const float* __restrict__ bias,    // [128]
    const int*   __restrict__ pos_ids  // [M_TOTAL]
) {
    extern __shared__ char dsm[];
    const uint32_t sbase = smem_u32(dsm);

    const int tid  = threadIdx.x;
    const int lane = tid & 31;
    const int warp = tid >> 5;
    const int wm   = warp >> 2;       // 0..1
    const int wn   = warp & 3;        // 0..3
    const int blockM = blockIdx.x * BM;

    float acc[4][4][4];
#pragma unroll
    for (int m = 0; m < 4; ++m)
#pragma unroll
        for (int n = 0; n < 4; ++n)
#pragma unroll
            for (int f = 0; f < 4; ++f) acc[m][n][f] = 0.0f;

    // ---- load mappings ----
    const int arow0 = tid >> 3;       // 0..31 (rows arow0 + 32*i)
    const int af    = tid & 7;        // float4 index within 32-float k-chunk
    const int bn    = tid & 127;      // B row (n)
    const int bp    = tid >> 7;       // 0..1: 32B half of the 64B row chunk

    // ldmatrix per-thread address pieces
    const int a_lr   = lane & 7;
    const int a_tile = lane >> 3;
    const uint32_t a_addr_base =
        (uint32_t)(((wm * 64 + (a_tile & 1) * 8 + a_lr) * BKP + (a_tile >> 1) * 8) * 2);
    const uint32_t b_addr_base =
        (uint32_t)(((wn * 32 + (a_tile >> 1) * 8 + a_lr) * BKP + (a_tile & 1) * 8) * 2);

    float4 aldg[4];
    const float4* Ag = reinterpret_cast<const float4*>(A);

    // B cp.async source/dest pieces
    const __half* bsrc_h = &g_Wt_h[(size_t)bn * HH + bp * 16];
    const __half* bsrc_l = &g_Wt_l[(size_t)bn * HH + bp * 16];
    const uint32_t bdst_off = (uint32_t)(bn * (BKP * 2) + bp * 32);

    // ---- prologue: chunk 0 into buf 0 ----
    {
        const uint32_t buf = sbase;
        cp16(buf + 1 * TILE_B + bdst_off,      bsrc_h);
        cp16(buf + 1 * TILE_B + bdst_off + 16, bsrc_h + 8);
        cp16(buf + 2 * TILE_B + bdst_off,      bsrc_l);
        cp16(buf + 2 * TILE_B + bdst_off + 16, bsrc_l + 8);
        cp_commit();
#pragma unroll
        for (int i = 0; i < 4; ++i)
            aldg[i] = Ag[((size_t)(blockM + arow0 + 32 * i) * HH) / 4 + af];
#pragma unroll
        for (int i = 0; i < 4; ++i) {
            uint32_t p0 = f2h2(aldg[i].x, aldg[i].y);
            uint32_t p1 = f2h2(aldg[i].z, aldg[i].w);
            uint32_t off = (uint32_t)((arow0 + 32 * i) * (BKP * 2) + af * 8);
            sts64(buf + off, p0, p1);
        }
        cp_wait0();
        __syncthreads();
    }

    for (int kt = 0; kt < NKT; ++kt) {
        const uint32_t cur = sbase + (kt & 1) * BUF_B;
        const uint32_t nxt = sbase + ((kt + 1) & 1) * BUF_B;
        const bool more = (kt + 1 < NKT);

        if (more) {
            const int k0 = (kt + 1) * BK;
            cp16(nxt + 1 * TILE_B + bdst_off,      bsrc_h + k0);
            cp16(nxt + 1 * TILE_B + bdst_off + 16, bsrc_h + k0 + 8);
            cp16(nxt + 2 * TILE_B + bdst_off,      bsrc_l + k0);
            cp16(nxt + 2 * TILE_B + bdst_off + 16, bsrc_l + k0 + 8);
            cp_commit();
#pragma unroll
            for (int i = 0; i < 4; ++i)
                aldg[i] = Ag[((size_t)(blockM + arow0 + 32 * i) * HH + k0) / 4 + af];
        }

        // ---- compute on cur: 2 k16 steps, 2 terms ----
        const uint32_t sA  = cur;
        const uint32_t sBH = cur + 1 * TILE_B, sBL = cur + 2 * TILE_B;
#pragma unroll
        for (int kk = 0; kk < BK; kk += 16) {
            uint32_t bh[2][4], bl[2][4];
#pragma unroll
            for (int n2 = 0; n2 < 2; ++n2) {
                uint32_t boff = b_addr_base + (uint32_t)((n2 * 16 * BKP + kk) * 2);
                ldsm4(sBH + boff, bh[n2][0], bh[n2][1], bh[n2][2], bh[n2][3]);
                ldsm4(sBL + boff, bl[n2][0], bl[n2][1], bl[n2][2], bl[n2][3]);
            }
#pragma unroll
            for (int m = 0; m < 4; ++m) {
                uint32_t aoff = a_addr_base + (uint32_t)((m * 16 * BKP + kk) * 2);
                uint32_t a0, a1, a2, a3;
                ldsm4(sA + aoff, a0, a1, a2, a3);
#pragma unroll
                for (int n = 0; n < 4; ++n) {
                    uint32_t b0 = bh[n >> 1][(n & 1) * 2];
                    uint32_t b1 = bh[n >> 1][(n & 1) * 2 + 1];
                    uint32_t c0 = bl[n >> 1][(n & 1) * 2];
                    uint32_t c1 = bl[n >> 1][(n & 1) * 2 + 1];
                    mma16816(acc[m][n], a0, a1, a2, a3, b0, b1);  // A16*Wh
                    mma16816(acc[m][n], a0, a1, a2, a3, c0, c1);  // A16*Wl
                }
            }
        }

        if (more) {
#pragma unroll
            for (int i = 0; i < 4; ++i) {
                uint32_t p0 = f2h2(aldg[i].x, aldg[i].y);
                uint32_t p1 = f2h2(aldg[i].z, aldg[i].w);
                uint32_t off = (uint32_t)((arow0 + 32 * i) * (BKP * 2) + af * 8);
                sts64(nxt + off, p0, p1);
            }
            cp_wait0();
        }
        __syncthreads();
    }

    // ---- epilogue: bias + RoPE + split store (all in registers) ----
    const float LN1E4_OVER_32 = 0.28782313662425574f;   // ln(10000)/32
#pragma unroll
    for (int n = 0; n < 4; ++n) {
        const int col  = wn * 32 + n * 8 + (lane & 3) * 2;   // even
        const bool is_q = (col < DD);
        const int dloc  = col & (DD - 1);
        const float fr  = __expf(-(float)(dloc >> 1) * LN1E4_OVER_32);
        const float b0 = bias[col], b1 = bias[col + 1];
        float* dst = is_q ? g_Q : g_K;
#pragma unroll
        for (int m = 0; m < 4; ++m) {
            const int ra = blockM + wm * 64 + m * 16 + (lane >> 2);
#pragma unroll
            for (int h = 0; h < 2; ++h) {
                const int r = ra + h * 8;
                const float pos = (float)__ldg(&pos_ids[r]);
                float s, c;
                sincosf(pos * fr, &s, &c);
                const float x0 = acc[m][n][2 * h]     + b0;
                const float x1 = acc[m][n][2 * h + 1] + b1;
                float2 y = make_float2(x0 * c - x1 * s, x1 * c + x0 * s);
                *reinterpret_cast<float2*>(&dst[(size_t)r * DD + dloc]) = y;
            }
        }
    }
}

// ---------------------------------------------------------------------------
// Relation gather + dot + mask. One warp per relation.
// ---------------------------------------------------------------------------
__global__ __launch_bounds__(256) void relation_kernel(
    const int*   __restrict__ rel_idx,  // [B*R, 4]
    const float* __restrict__ mask,     // [B*R]
    float*       __restrict__ out       // [B*R]
) {
    const int warp = (blockIdx.x * blockDim.x + threadIdx.x) >> 5;
    const int lane = threadIdx.x & 31;
    if (warp >= BB * RR) return;

    const int b    = warp / RR;
    const int4 idx = reinterpret_cast<const int4*>(rel_idx)[warp];
    const int base = b * SS;

    // lanes 0-15: q0.k2 on float4; lanes 16-31: q1.k3
    const int seg  = lane >> 4;          // 0 or 1
    const int sl   = lane & 15;
    const int qrow = base + (seg ? idx.y : idx.x);
    const int krow = base + (seg ? idx.w : idx.z);
    float4 qa = reinterpret_cast<const float4*>(&g_Q[(size_t)qrow * DD])[sl];
    float4 ka = reinterpret_cast<const float4*>(&g_K[(size_t)krow * DD])[sl];
    float sum = qa.x * ka.x + qa.y * ka.y + qa.z * ka.z + qa.w * ka.w;

#pragma unroll
    for (int off = 16; off > 0; off >>= 1)
        sum += __shfl_xor_sync(0xffffffffu, sum, off);

    if (lane == 0) {
        const float m = mask[warp];
        out[warp] = (sum + (1.0f - m) * -1e12f) * 0.125f;  // 1/sqrt(64)
    }
}

extern "C" void kernel_launch(void* const* d_in, const int* in_sizes, int n_in,
                              void* d_out, int out_size) {
    const float* lhs  = (const float*)d_in[0];   // [B,S,H]
    const float* W    = (const float*)d_in[1];   // [H,128]
    const float* bias = (const float*)d_in[2];   // [128]
    const int*   pos  = (const int*)d_in[3];     // [B,S]
    const int*   ridx = (const int*)d_in[4];     // [B,R,4]
    const float* lm   = (const float*)d_in[5];   // [B,R]
    float* out = (float*)d_out;                  // [B,R]

    static bool attr_set = false;
    if (!attr_set) {
        cudaFuncSetAttribute(gemm_mma_kernel,
                             cudaFuncAttributeMaxDynamicSharedMemorySize, SMEM_DYN);
        attr_set = true;
    }
    prep_w_kernel<<<dim3(32, 4), 256>>>(W);
    gemm_mma_kernel<<<M_TOTAL / BM, 256, SMEM_DYN>>>(lhs, bias, pos);
    relation_kernel<<<(BB * RR + 7) / 8, 256>>>(ridx, lm, out);
}

// round 7
// speedup vs baseline: 3.9891x; 1.4729x over previous
#include <cuda_runtime.h>
#include <cuda_fp16.h>
#include <cstdint>

#define BB 16
#define SS 2048
#define HH 1024
#define DD 64
#define RR 2048
#define M_TOTAL (BB*SS)          // 32768 rows
#define NN 128                   // output cols (q | k)

#define BM 128
#define BN 128
#define BK 32
#define BKP 40                   // padded row length in fp16 (80B rows)
#define NKT (HH/BK)              // 32 k-chunks

// dynamic SMEM: per buffer [A16 | WH], each tile 128*40*2 = 10240 B
#define TILE_B   (128*BKP*2)
#define BUF_B    (2*TILE_B)      // 20480
#define SMEM_DYN (2*BUF_B)       // 40960

// Scratch: Q/K in fp16
__device__ __half g_Q[M_TOTAL * DD];
__device__ __half g_K[M_TOTAL * DD];
__device__ __half g_Wt_h[NN * HH];   // W^T fp16, [128][1024] K-major

// ---------------- helpers ----------------
__device__ __forceinline__ uint32_t smem_u32(const void* p) {
    uint32_t a;
    asm("{ .reg .u64 t; cvta.to.shared.u64 t, %1; cvt.u32.u64 %0, t; }"
        : "=r"(a) : "l"(p));
    return a;
}
// pack f16(lo),f16(hi): first PTX source lands in HIGH half
__device__ __forceinline__ uint32_t f2h2(float lo, float hi) {
    uint32_t r;
    asm("cvt.rn.f16x2.f32 %0, %1, %2;" : "=r"(r) : "f"(hi), "f"(lo));
    return r;
}
__device__ __forceinline__ void sts64(uint32_t addr, uint32_t a, uint32_t b) {
    asm volatile("st.shared.v2.b32 [%0], {%1,%2};" :: "r"(addr), "r"(a), "r"(b) : "memory");
}
__device__ __forceinline__ void cp16(uint32_t daddr, const void* src) {
    asm volatile("cp.async.cg.shared.global [%0], [%1], 16;"
                 :: "r"(daddr), "l"(src) : "memory");
}
__device__ __forceinline__ void cp_commit() {
    asm volatile("cp.async.commit_group;" ::: "memory");
}
__device__ __forceinline__ void cp_wait0() {
    asm volatile("cp.async.wait_group 0;" ::: "memory");
}
__device__ __forceinline__ void ldsm4(uint32_t addr, uint32_t& r0, uint32_t& r1,
                                      uint32_t& r2, uint32_t& r3) {
    asm volatile("ldmatrix.sync.aligned.m8n8.x4.shared.b16 {%0,%1,%2,%3}, [%4];"
                 : "=r"(r0), "=r"(r1), "=r"(r2), "=r"(r3) : "r"(addr));
}
__device__ __forceinline__ void mma16816(float* c, uint32_t a0, uint32_t a1,
                                         uint32_t a2, uint32_t a3,
                                         uint32_t b0, uint32_t b1) {
    asm volatile(
        "mma.sync.aligned.m16n8k16.row.col.f32.f16.f16.f32 "
        "{%0,%1,%2,%3}, {%4,%5,%6,%7}, {%8,%9}, {%0,%1,%2,%3};"
        : "+f"(c[0]), "+f"(c[1]), "+f"(c[2]), "+f"(c[3])
        : "r"(a0), "r"(a1), "r"(a2), "r"(a3), "r"(b0), "r"(b1));
}

// ---------------------------------------------------------------------------
// Prep: W [1024][128] fp32 -> Wt_h [128][1024] fp16, tiled transpose
// ---------------------------------------------------------------------------
__global__ __launch_bounds__(256) void prep_w_kernel(const float* __restrict__ W) {
    __shared__ float t[32][33];
    const int k0 = blockIdx.x * 32;       // 32 tiles
    const int n0 = blockIdx.y * 32;       // 4 tiles
    const int r = threadIdx.x >> 5, c = threadIdx.x & 31;
#pragma unroll
    for (int i = 0; i < 4; ++i)
        t[r + 8 * i][c] = W[(size_t)(k0 + r + 8 * i) * NN + n0 + c];
    __syncthreads();
#pragma unroll
    for (int i = 0; i < 4; ++i) {
        const int n = n0 + r + 8 * i, k = k0 + c;
        g_Wt_h[(size_t)n * HH + k] = __float2half_rn(t[c][r + 8 * i]);
    }
}

// ---------------------------------------------------------------------------
// GEMM via mma.sync fp16 (single term), double-buffered, fused bias + RoPE.
// CTA: M=128, N=128, K=1024. 8 warps (2x4), warp tile 64x32. fp16 Q/K out.
// ---------------------------------------------------------------------------
__global__ __launch_bounds__(256, 2) void gemm_mma_kernel(
    const float* __restrict__ A,       // [M_TOTAL, 1024]
    const float* __restrict__ bias,    // [128]
    const int*   __restrict__ pos_ids  // [M_TOTAL]
) {
    extern __shared__ char dsm[];
    const uint32_t sbase = smem_u32(dsm);

    const int tid  = threadIdx.x;
    const int lane = tid & 31;
    const int warp = tid >> 5;
    const int wm   = warp >> 2;       // 0..1
    const int wn   = warp & 3;        // 0..3
    const int blockM = blockIdx.x * BM;

    float acc[4][4][4];
#pragma unroll
    for (int m = 0; m < 4; ++m)
#pragma unroll
        for (int n = 0; n < 4; ++n)
#pragma unroll
            for (int f = 0; f < 4; ++f) acc[m][n][f] = 0.0f;

    // ---- load mappings ----
    const int arow0 = tid >> 3;       // 0..31 (rows arow0 + 32*i)
    const int af    = tid & 7;        // float4 index within 32-float k-chunk
    const int bn    = tid & 127;      // B row (n)
    const int bp    = tid >> 7;       // 0..1: 32B half of the 64B row chunk

    // ldmatrix per-thread address pieces
    const int a_lr   = lane & 7;
    const int a_tile = lane >> 3;
    const uint32_t a_addr_base =
        (uint32_t)(((wm * 64 + (a_tile & 1) * 8 + a_lr) * BKP + (a_tile >> 1) * 8) * 2);
    const uint32_t b_addr_base =
        (uint32_t)(((wn * 32 + (a_tile >> 1) * 8 + a_lr) * BKP + (a_tile & 1) * 8) * 2);

    float4 aldg[4];
    const float4* Ag = reinterpret_cast<const float4*>(A);

    // B cp.async source/dest pieces
    const __half* bsrc_h = &g_Wt_h[(size_t)bn * HH + bp * 16];
    const uint32_t bdst_off = (uint32_t)(bn * (BKP * 2) + bp * 32);

    // ---- prologue: chunk 0 into buf 0 ----
    {
        const uint32_t buf = sbase;
        cp16(buf + TILE_B + bdst_off,      bsrc_h);
        cp16(buf + TILE_B + bdst_off + 16, bsrc_h + 8);
        cp_commit();
#pragma unroll
        for (int i = 0; i < 4; ++i)
            aldg[i] = Ag[((size_t)(blockM + arow0 + 32 * i) * HH) / 4 + af];
#pragma unroll
        for (int i = 0; i < 4; ++i) {
            uint32_t p0 = f2h2(aldg[i].x, aldg[i].y);
            uint32_t p1 = f2h2(aldg[i].z, aldg[i].w);
            uint32_t off = (uint32_t)((arow0 + 32 * i) * (BKP * 2) + af * 8);
            sts64(buf + off, p0, p1);
        }
        cp_wait0();
        __syncthreads();
    }

    for (int kt = 0; kt < NKT; ++kt) {
        const uint32_t cur = sbase + (kt & 1) * BUF_B;
        const uint32_t nxt = sbase + ((kt + 1) & 1) * BUF_B;
        const bool more = (kt + 1 < NKT);

        if (more) {
            const int k0 = (kt + 1) * BK;
            cp16(nxt + TILE_B + bdst_off,      bsrc_h + k0);
            cp16(nxt + TILE_B + bdst_off + 16, bsrc_h + k0 + 8);
            cp_commit();
#pragma unroll
            for (int i = 0; i < 4; ++i)
                aldg[i] = Ag[((size_t)(blockM + arow0 + 32 * i) * HH + k0) / 4 + af];
        }

        // ---- compute on cur: 2 k16 steps ----
        const uint32_t sA = cur, sBH = cur + TILE_B;
#pragma unroll
        for (int kk = 0; kk < BK; kk += 16) {
            uint32_t bh[2][4];
#pragma unroll
            for (int n2 = 0; n2 < 2; ++n2) {
                uint32_t boff = b_addr_base + (uint32_t)((n2 * 16 * BKP + kk) * 2);
                ldsm4(sBH + boff, bh[n2][0], bh[n2][1], bh[n2][2], bh[n2][3]);
            }
#pragma unroll
            for (int m = 0; m < 4; ++m) {
                uint32_t aoff = a_addr_base + (uint32_t)((m * 16 * BKP + kk) * 2);
                uint32_t a0, a1, a2, a3;
                ldsm4(sA + aoff, a0, a1, a2, a3);
#pragma unroll
                for (int n = 0; n < 4; ++n)
                    mma16816(acc[m][n], a0, a1, a2, a3,
                             bh[n >> 1][(n & 1) * 2], bh[n >> 1][(n & 1) * 2 + 1]);
            }
        }

        if (more) {
#pragma unroll
            for (int i = 0; i < 4; ++i) {
                uint32_t p0 = f2h2(aldg[i].x, aldg[i].y);
                uint32_t p1 = f2h2(aldg[i].z, aldg[i].w);
                uint32_t off = (uint32_t)((arow0 + 32 * i) * (BKP * 2) + af * 8);
                sts64(nxt + off, p0, p1);
            }
            cp_wait0();
        }
        __syncthreads();
    }

    // ---- epilogue: bias + RoPE + fp16 split store ----
    const float LN1E4_OVER_32 = 0.28782313662425574f;   // ln(10000)/32
#pragma unroll
    for (int n = 0; n < 4; ++n) {
        const int col  = wn * 32 + n * 8 + (lane & 3) * 2;   // even
        const bool is_q = (col < DD);
        const int dloc  = col & (DD - 1);
        const float fr  = __expf(-(float)(dloc >> 1) * LN1E4_OVER_32);
        const float b0 = bias[col], b1 = bias[col + 1];
        __half* dst = is_q ? g_Q : g_K;
#pragma unroll
        for (int m = 0; m < 4; ++m) {
            const int ra = blockM + wm * 64 + m * 16 + (lane >> 2);
#pragma unroll
            for (int h = 0; h < 2; ++h) {
                const int r = ra + h * 8;
                const float pos = (float)__ldg(&pos_ids[r]);
                float s, c;
                sincosf(pos * fr, &s, &c);
                const float x0 = acc[m][n][2 * h]     + b0;
                const float x1 = acc[m][n][2 * h + 1] + b1;
                __half2 y = __floats2half2_rn(x0 * c - x1 * s, x1 * c + x0 * s);
                *reinterpret_cast<__half2*>(&dst[(size_t)r * DD + dloc]) = y;
            }
        }
    }
}

// ---------------------------------------------------------------------------
// Relation gather + dot + mask. One warp per relation, fp16 Q/K.
// ---------------------------------------------------------------------------
__global__ __launch_bounds__(256) void relation_kernel(
    const int*   __restrict__ rel_idx,  // [B*R, 4]
    const float* __restrict__ mask,     // [B*R]
    float*       __restrict__ out       // [B*R]
) {
    const int warp = (blockIdx.x * blockDim.x + threadIdx.x) >> 5;
    const int lane = threadIdx.x & 31;
    if (warp >= BB * RR) return;

    const int b    = warp / RR;
    const int4 idx = reinterpret_cast<const int4*>(rel_idx)[warp];
    const int base = b * SS;

    // lanes 0-15: q0.k2; lanes 16-31: q1.k3. Each lane: 4 halves (8B).
    const int seg  = lane >> 4;          // 0 or 1
    const int sl   = lane & 15;
    const int qrow = base + (seg ? idx.y : idx.x);
    const int krow = base + (seg ? idx.w : idx.z);
    uint2 qa = reinterpret_cast<const uint2*>(&g_Q[(size_t)qrow * DD])[sl];
    uint2 ka = reinterpret_cast<const uint2*>(&g_K[(size_t)krow * DD])[sl];

    float2 q0 = __half22float2(*reinterpret_cast<__half2*>(&qa.x));
    float2 q1 = __half22float2(*reinterpret_cast<__half2*>(&qa.y));
    float2 k0 = __half22float2(*reinterpret_cast<__half2*>(&ka.x));
    float2 k1 = __half22float2(*reinterpret_cast<__half2*>(&ka.y));
    float sum = q0.x * k0.x + q0.y * k0.y + q1.x * k1.x + q1.y * k1.y;

#pragma unroll
    for (int off = 16; off > 0; off >>= 1)
        sum += __shfl_xor_sync(0xffffffffu, sum, off);

    if (lane == 0) {
        const float m = mask[warp];
        out[warp] = (sum + (1.0f - m) * -1e12f) * 0.125f;  // 1/sqrt(64)
    }
}

extern "C" void kernel_launch(void* const* d_in, const int* in_sizes, int n_in,
                              void* d_out, int out_size) {
    const float* lhs  = (const float*)d_in[0];   // [B,S,H]
    const float* W    = (const float*)d_in[1];   // [H,128]
    const float* bias = (const float*)d_in[2];   // [128]
    const int*   pos  = (const int*)d_in[3];     // [B,S]
    const int*   ridx = (const int*)d_in[4];     // [B,R,4]
    const float* lm   = (const float*)d_in[5];   // [B,R]
    float* out = (float*)d_out;                  // [B,R]

    static bool attr_set = false;
    if (!attr_set) {
        cudaFuncSetAttribute(gemm_mma_kernel,
                             cudaFuncAttributeMaxDynamicSharedMemorySize, SMEM_DYN);
        attr_set = true;
    }
    prep_w_kernel<<<dim3(32, 4), 256>>>(W);
    gemm_mma_kernel<<<M_TOTAL / BM, 256, SMEM_DYN>>>(lhs, bias, pos);
    relation_kernel<<<(BB * RR + 7) / 8, 256>>>(ridx, lm, out);
}